// round 3
// baseline (speedup 1.0000x reference)
#include <cuda_runtime.h>
#include <cstdint>

// Flash attention, tf32 mma.sync path.
// B=8,H=8,N=1024,d=128. out = softmax(mask(QK^T/8, adj)) @ V, (B,H,N,d) contiguous.

namespace {
constexpr int Nq  = 1024;
constexpr int D   = 128;
constexpr int BR  = 128;            // query rows per CTA
constexpr int BC  = 32;             // key cols per tile
constexpr int NT  = Nq / BC;        // 32 tiles
constexpr int TPB = 256;            // 8 warps, 16 query rows each

constexpr int QS = D + 4;           // 132: bank = 4g+c (unique for g0..7,c0..3)
constexpr int KSs = D + 4;          // 132: same pattern (rows span g)
constexpr int VS = D + 8;           // 136: bank = 8c+g (rows span c)
constexpr int PS = BC + 4;          // 36:  bank = 4g+c

constexpr int SM_Q = BR * QS;               // 16896
constexpr int SM_K = 2 * BC * KSs;          // 8448
constexpr int SM_V = 2 * BC * VS;           // 8704
constexpr int SM_P = 8 * 16 * PS;           // 4608
constexpr int SMEM_BYTES = (SM_Q + SM_K + SM_V + SM_P) * 4;  // 154,624 B
}

__device__ __forceinline__ float to_tf32(float x) {
    float r;
    asm("cvt.rna.tf32.f32 %0, %1;" : "=f"(r) : "f"(x));
    return r;
}

__device__ __forceinline__ uint32_t smem_u32(const void* p) {
    return (uint32_t)__cvta_generic_to_shared(p);
}

__device__ __forceinline__ void cp_async16(uint32_t s, const void* g) {
    asm volatile("cp.async.cg.shared.global [%0], [%1], 16;" :: "r"(s), "l"(g));
}

__device__ __forceinline__ void mma_tf32(float& d0, float& d1, float& d2, float& d3,
                                         uint32_t a0, uint32_t a1, uint32_t a2, uint32_t a3,
                                         uint32_t b0, uint32_t b1) {
    asm volatile("mma.sync.aligned.m16n8k8.row.col.f32.tf32.tf32.f32 "
                 "{%0,%1,%2,%3},{%4,%5,%6,%7},{%8,%9},{%0,%1,%2,%3};"
                 : "+f"(d0), "+f"(d1), "+f"(d2), "+f"(d3)
                 : "r"(a0), "r"(a1), "r"(a2), "r"(a3), "r"(b0), "r"(b1));
}

__device__ __forceinline__ uint32_t fu(float x) { return __float_as_uint(x); }

// FMA-only exp: avoids the 0.5/cyc/SM MUFU.EX2 floor (503us chip-wide for 67M exps).
// Valid for x <= ~0.1; clamps below -87. |rel err| ~1e-6.
__device__ __forceinline__ float exp_fast(float x) {
    x = fmaxf(x, -87.0f);
    float t = x * 1.4426950408889634f;
    float r = t + 12582912.0f;                       // 1.5*2^23 magic round
    int   n = __float_as_int(r) - 0x4B400000;        // integer part (two's complement ok)
    float f = t - (r - 12582912.0f);                 // f in [-0.5, 0.5]
    float p = 0.00133335581f;
    p = fmaf(p, f, 0.00961812910f);
    p = fmaf(p, f, 0.0555041087f);
    p = fmaf(p, f, 0.240226507f);
    p = fmaf(p, f, 0.693147180f);
    p = fmaf(p, f, 1.0f);                            // p = 2^f in [0.707, 1.415]
    return __int_as_float(__float_as_int(p) + (n << 23));
}

__global__ __launch_bounds__(TPB, 1)
void fa_tf32_kernel(const float* __restrict__ Qg, const float* __restrict__ Kg,
                    const float* __restrict__ Vg, const int* __restrict__ adj,
                    float* __restrict__ Out)
{
    extern __shared__ float sm[];
    float* Qs = sm;                       // [128][132]
    float* Kb = Qs + SM_Q;                // [2][32][132]
    float* Vb = Kb + SM_K;                // [2][32][136]
    float* Pa = Vb + SM_V;                // [8][16][36]

    const int tid  = threadIdx.x;
    const int lane = tid & 31;
    const int w    = tid >> 5;
    const int g    = lane >> 2;           // groupID 0..7
    const int c    = lane & 3;            // threadID_in_group 0..3
    const int head = blockIdx.x >> 3;
    const int rt   = blockIdx.x & 7;
    const int row0 = rt * BR;
    const int q0   = w * 16;              // warp's query-row block within CTA

    const float* Qh = Qg + ((size_t)head * Nq + row0) * D;
    const float* Kh = Kg + (size_t)head * Nq * D;
    const float* Vh = Vg + (size_t)head * Nq * D;

    // ---- stage Q (128x128), RNA-rounded to tf32 ----
    #pragma unroll
    for (int i = 0; i < 16; ++i) {
        int f  = tid + i * TPB;
        int r  = f >> 5, c4 = (f & 31) * 4;
        float4 v = *(const float4*)(Qh + r * D + c4);
        float* d = Qs + r * QS + c4;
        d[0] = to_tf32(v.x); d[1] = to_tf32(v.y);
        d[2] = to_tf32(v.z); d[3] = to_tf32(v.w);
    }
    // ---- stage K tile 0 (RNA-rounded) + V tile 0 (cp.async, truncation ok) ----
    #pragma unroll
    for (int i = 0; i < 4; ++i) {
        int f  = tid + i * TPB;
        int r  = f >> 5, c4 = (f & 31) * 4;
        float4 v = *(const float4*)(Kh + r * D + c4);
        float* d = Kb + r * KSs + c4;
        d[0] = to_tf32(v.x); d[1] = to_tf32(v.y);
        d[2] = to_tf32(v.z); d[3] = to_tf32(v.w);
        cp_async16(smem_u32(Vb + r * VS + c4), Vh + r * D + c4);
    }
    asm volatile("cp.async.commit_group;" ::: "memory");

    float o[16][4];
    #pragma unroll
    for (int j = 0; j < 16; ++j)
        #pragma unroll
        for (int i = 0; i < 4; ++i) o[j][i] = 0.f;
    float m0 = -9e15f, m1 = -9e15f, l0 = 0.f, l1 = 0.f;
    int buf = 0;

    float* Pw = Pa + w * 16 * PS;

    #pragma unroll 1
    for (int kt = 0; kt < NT; ++kt) {
        asm volatile("cp.async.wait_group 0;" ::: "memory");
        __syncthreads();

        const float* Kc = Kb + buf * BC * KSs;
        const float* Vc = Vb + buf * BC * VS;
        float*       Kn = Kb + (buf ^ 1) * BC * KSs;
        float*       Vn = Vb + (buf ^ 1) * BC * VS;

        // prefetch next K into registers, launch next V cp.async
        float4 kp[4];
        const bool more = (kt + 1 < NT);
        if (more) {
            const float* Kg2 = Kh + (size_t)(kt + 1) * BC * D;
            const float* Vg2 = Vh + (size_t)(kt + 1) * BC * D;
            #pragma unroll
            for (int i = 0; i < 4; ++i) {
                int f = tid + i * TPB;
                int r = f >> 5, c4 = (f & 31) * 4;
                kp[i] = *(const float4*)(Kg2 + r * D + c4);
                cp_async16(smem_u32(Vn + r * VS + c4), Vg2 + r * D + c4);
            }
            asm volatile("cp.async.commit_group;" ::: "memory");
        }

        // ---- S = Q K^T : warp tile 16x32, 4 n-tiles, 16 k-steps ----
        float s[4][4];
        #pragma unroll
        for (int j = 0; j < 4; ++j)
            #pragma unroll
            for (int i = 0; i < 4; ++i) s[j][i] = 0.f;

        const float* qa  = Qs + (q0 + g) * QS + c;
        const float* kb0 = Kc + g * KSs + c;
        #pragma unroll
        for (int ks = 0; ks < 16; ++ks) {
            uint32_t a0 = fu(qa[8 * ks]);
            uint32_t a1 = fu(qa[8 * QS + 8 * ks]);
            uint32_t a2 = fu(qa[8 * ks + 4]);
            uint32_t a3 = fu(qa[8 * QS + 8 * ks + 4]);
            #pragma unroll
            for (int j = 0; j < 4; ++j) {
                uint32_t b0 = fu(kb0[j * 8 * KSs + 8 * ks]);
                uint32_t b1 = fu(kb0[j * 8 * KSs + 8 * ks + 4]);
                mma_tf32(s[j][0], s[j][1], s[j][2], s[j][3], a0, a1, a2, a3, b0, b1);
            }
        }

        // ---- mask + scale (exact reference constants) ----
        const int qr = row0 + q0 + g;
        #pragma unroll
        for (int j = 0; j < 4; ++j) {
            int gc = kt * BC + 8 * j + 2 * c;
            int2 ma = *(const int2*)(adj + (size_t)qr * Nq + gc);
            int2 mb = *(const int2*)(adj + (size_t)(qr + 8) * Nq + gc);
            s[j][0] = (ma.x > 0) ? s[j][0] * 0.125f : -9e15f;
            s[j][1] = (ma.y > 0) ? s[j][1] * 0.125f : -9e15f;
            s[j][2] = (mb.x > 0) ? s[j][2] * 0.125f : -9e15f;
            s[j][3] = (mb.y > 0) ? s[j][3] * 0.125f : -9e15f;
        }

        // ---- online softmax: rows g (slots 0,1) and g+8 (slots 2,3); reduce over 4-lane group ----
        float tm0 = fmaxf(fmaxf(s[0][0], s[0][1]), fmaxf(s[1][0], s[1][1]));
        tm0 = fmaxf(tm0, fmaxf(fmaxf(s[2][0], s[2][1]), fmaxf(s[3][0], s[3][1])));
        float tm1 = fmaxf(fmaxf(s[0][2], s[0][3]), fmaxf(s[1][2], s[1][3]));
        tm1 = fmaxf(tm1, fmaxf(fmaxf(s[2][2], s[2][3]), fmaxf(s[3][2], s[3][3])));
        tm0 = fmaxf(tm0, __shfl_xor_sync(0xffffffffu, tm0, 1));
        tm0 = fmaxf(tm0, __shfl_xor_sync(0xffffffffu, tm0, 2));
        tm1 = fmaxf(tm1, __shfl_xor_sync(0xffffffffu, tm1, 1));
        tm1 = fmaxf(tm1, __shfl_xor_sync(0xffffffffu, tm1, 2));

        float mn0 = fmaxf(m0, tm0), mn1 = fmaxf(m1, tm1);
        float sc0 = exp_fast(m0 - mn0), sc1 = exp_fast(m1 - mn1);
        m0 = mn0; m1 = mn1;

        float p[4][4];
        float rs0 = 0.f, rs1 = 0.f;
        #pragma unroll
        for (int j = 0; j < 4; ++j) {
            p[j][0] = exp_fast(s[j][0] - mn0);
            p[j][1] = exp_fast(s[j][1] - mn0);
            p[j][2] = exp_fast(s[j][2] - mn1);
            p[j][3] = exp_fast(s[j][3] - mn1);
            rs0 += p[j][0] + p[j][1];
            rs1 += p[j][2] + p[j][3];
        }
        rs0 += __shfl_xor_sync(0xffffffffu, rs0, 1);
        rs0 += __shfl_xor_sync(0xffffffffu, rs0, 2);
        rs1 += __shfl_xor_sync(0xffffffffu, rs1, 1);
        rs1 += __shfl_xor_sync(0xffffffffu, rs1, 2);
        l0 = l0 * sc0 + rs0;
        l1 = l1 * sc1 + rs1;

        #pragma unroll
        for (int j2 = 0; j2 < 16; ++j2) {
            o[j2][0] *= sc0; o[j2][1] *= sc0;
            o[j2][2] *= sc1; o[j2][3] *= sc1;
        }

        // ---- P -> warp-private smem (A-fragment relayout), warp-local only ----
        #pragma unroll
        for (int j = 0; j < 4; ++j) {
            *(float2*)(Pw + g * PS + 8 * j + 2 * c)       = make_float2(p[j][0], p[j][1]);
            *(float2*)(Pw + (g + 8) * PS + 8 * j + 2 * c) = make_float2(p[j][2], p[j][3]);
        }
        __syncwarp();

        // ---- O += P @ V : 16 n-tiles over d=128, 4 k-steps ----
        const float* pa  = Pw + g * PS + c;
        const float* vb0 = Vc + c * VS + g;
        #pragma unroll
        for (int kk = 0; kk < 4; ++kk) {
            uint32_t a0 = fu(pa[8 * kk]);
            uint32_t a1 = fu(pa[8 * PS + 8 * kk]);
            uint32_t a2 = fu(pa[8 * kk + 4]);
            uint32_t a3 = fu(pa[8 * PS + 8 * kk + 4]);
            #pragma unroll
            for (int j2 = 0; j2 < 16; ++j2) {
                uint32_t b0 = fu(vb0[(8 * kk) * VS + 8 * j2]);
                uint32_t b1 = fu(vb0[(8 * kk + 4) * VS + 8 * j2]);
                mma_tf32(o[j2][0], o[j2][1], o[j2][2], o[j2][3], a0, a1, a2, a3, b0, b1);
            }
        }

        // ---- store prefetched K (RNA) into next buffer; safe: barrier at kt start ----
        if (more) {
            #pragma unroll
            for (int i = 0; i < 4; ++i) {
                int f = tid + i * TPB;
                int r = f >> 5, c4 = (f & 31) * 4;
                float* d = Kn + r * KSs + c4;
                d[0] = to_tf32(kp[i].x); d[1] = to_tf32(kp[i].y);
                d[2] = to_tf32(kp[i].z); d[3] = to_tf32(kp[i].w);
            }
        }
        buf ^= 1;
    }

    // ---- epilogue: normalize + store ----
    float inv0 = 1.0f / l0;
    float inv1 = 1.0f / l1;
    float* orow0 = Out + ((size_t)head * Nq + row0 + q0 + g) * D;
    float* orow1 = orow0 + 8 * D;
    #pragma unroll
    for (int j2 = 0; j2 < 16; ++j2) {
        *(float2*)(orow0 + 8 * j2 + 2 * c) = make_float2(o[j2][0] * inv0, o[j2][1] * inv0);
        *(float2*)(orow1 + 8 * j2 + 2 * c) = make_float2(o[j2][2] * inv1, o[j2][3] * inv1);
    }
}

extern "C" void kernel_launch(void* const* d_in, const int* in_sizes, int n_in,
                              void* d_out, int out_size)
{
    const float* Q   = (const float*)d_in[0];
    const float* K   = (const float*)d_in[1];
    const float* V   = (const float*)d_in[2];
    const int*   adj = (const int*)d_in[3];
    float*       out = (float*)d_out;

    cudaFuncSetAttribute(fa_tf32_kernel,
                         cudaFuncAttributeMaxDynamicSharedMemorySize, SMEM_BYTES);

    dim3 grid(64 * (Nq / BR));   // 64 heads * 8 row-tiles = 512 CTAs
    fa_tf32_kernel<<<grid, TPB, SMEM_BYTES>>>(Q, K, V, adj, out);
}